// round 7
// baseline (speedup 1.0000x reference)
#include <cuda_runtime.h>
#include <cuda_fp16.h>
#include <math.h>

#define B_  64
#define M_  16
#define A_  128
#define H_  128
#define P_  16
#define NATOM 100
#define NFP   2048
#define NTAB  (NATOM + NFP)     // 2148
#define GRID  128
#define NTHR  1024
#define RPB   17                // table rows per block in proj phase

// Dynamic smem layout (bytes):
//   r1:    [0, 10240)            E-tile (phase A) / gather indices
//   r2:    [10240, 45056)        phase A partials / phase C partials / head arrays
//   atab:  [45056, 70656)        smem copy of the 100-row atom table (fp16)
#define SMEM_R1_OFF   0
#define SMEM_R2_OFF   10240
#define SMEM_AT_OFF   45056
#define SMEM_DYN      70656

// Scratch (__device__ globals: allocation-free rule)
__device__ __half   g_proj_h[NTAB * H_];    // projected tables, fp16 (0.55 MB, L2-resident)
__device__ float    g_mol[B_ * M_ * H_];    // per-molecule mean embeddings
__device__ unsigned g_arr[GRID];            // flat-barrier arrival slots (monotonic)
__device__ unsigned g_flag[GRID];           // per-block molecule-done flags (monotonic)

// Flat grid barrier: per-block arrival slot (no atomic contention), warp 0 of
// every block polls all 128 slots. Monotonic counters -> graph-replay-safe.
// All GRID=128 blocks are co-resident (1 block/SM), so the spin cannot deadlock.
// Returns the epoch (== launch ordinal), also the target for g_flag waits.
__device__ __forceinline__ unsigned flat_barrier_epoch(unsigned* s_ep) {
    __threadfence();
    __syncthreads();
    const int tid = threadIdx.x;
    if (tid < 32) {
        unsigned target = 0;
        if (tid == 0) target = atomicAdd(&g_arr[blockIdx.x], 1u) + 1u;  // own slot
        target = __shfl_sync(0xFFFFFFFFu, target, 0);
        const volatile unsigned* arr = (const volatile unsigned*)g_arr;
        for (;;) {
            unsigned m = 0xFFFFFFFFu;
            #pragma unroll
            for (int i = 0; i < 4; i++) {
                unsigned v = arr[tid * 4 + i];
                m = (v < m) ? v : m;
            }
            m = __reduce_min_sync(0xFFFFFFFFu, m);
            if (m >= target) break;
        }
        if (tid == 0) *s_ep = target;
    }
    __syncthreads();
    return *s_ep;
}

__global__ __launch_bounds__(NTHR, 1)
void fused_kernel(const int*   __restrict__ atom_features,
                  const int*   __restrict__ fingerprints,
                  const float* __restrict__ phys,
                  const float* __restrict__ ratios,
                  const float* __restrict__ atom_emb,
                  const float* __restrict__ fp_emb,
                  const float* __restrict__ W_in,
                  const float* __restrict__ b_in,
                  const float* __restrict__ ln_g,
                  const float* __restrict__ ln_b,
                  const float* __restrict__ W1,
                  const float* __restrict__ b1,
                  const float* __restrict__ W2,
                  const float* __restrict__ b2,
                  float* __restrict__ out) {
    extern __shared__ __align__(16) char smem[];
    float* s_r1   = (float*)(smem + SMEM_R1_OFF);
    float* s_r2   = (float*)(smem + SMEM_R2_OFF);
    __half* s_atab = (__half*)(smem + SMEM_AT_OFF);
    __shared__ unsigned s_ep;

    const int tid = threadIdx.x;
    const int blk = blockIdx.x;

    // ---------------- Phase A: projected tables -> g_proj_h (fp16) -----------
    // Blocks 0..5: 100 atom rows (+b_in). Blocks 6..127: 2048 fp rows.
    // h = tid&127 (output col), ks = (tid>>7)&3 (32 K-steps), rh = tid>>9 (row half).
    {
        float* s_eT = s_r1;                     // [d][r] stride 20
        float* s_p  = s_r2;                     // [ks][r][h]
        const int h  = tid & 127;
        const int ks = (tid >> 7) & 3;
        const int rh = tid >> 9;
        const int r0 = rh ? 8 : 0;
        const bool is_atom = (blk < 6);
        const int lrow0 = is_atom ? blk * RPB : (blk - 6) * RPB;
        const int nrows = is_atom ? NATOM : NFP;
        const int wbase = is_atom ? 0 : (H_ * H_);

        for (int i = tid; i < RPB * H_; i += NTHR) {
            int r = i >> 7, d = i & 127;
            int t = lrow0 + r;
            float v = 0.0f;
            if (t < nrows) v = is_atom ? atom_emb[t * H_ + d] : fp_emb[t * H_ + d];
            s_eT[d * 20 + r] = v;
        }
        __syncthreads();

        const float* __restrict__ Wp = W_in + wbase + h;
        const int d0 = ks * 32;

        float acc[9];
        #pragma unroll
        for (int r = 0; r < 9; r++) acc[r] = 0.0f;

        #pragma unroll
        for (int chunk = 0; chunk < 2; chunk++) {
            float wreg[16];
            #pragma unroll
            for (int i = 0; i < 16; i++) wreg[i] = Wp[(d0 + chunk * 16 + i) * H_];

            #pragma unroll
            for (int dd = 0; dd < 16; dd++) {
                const float w = wreg[dd];
                const float* e = s_eT + (d0 + chunk * 16 + dd) * 20 + r0;
                const float4 e0 = *(const float4*)(e);
                const float4 e1 = *(const float4*)(e + 4);
                acc[0] += e0.x * w; acc[1] += e0.y * w; acc[2] += e0.z * w; acc[3] += e0.w * w;
                acc[4] += e1.x * w; acc[5] += e1.y * w; acc[6] += e1.z * w; acc[7] += e1.w * w;
                if (rh) acc[8] += e[8] * w;
            }
        }

        const int nr = rh ? 9 : 8;
        #pragma unroll
        for (int r = 0; r < 9; r++)
            if (r < nr) s_p[(ks * RPB + r0 + r) * H_ + h] = acc[r];
        __syncthreads();

        const int NP = RPB * H_;
        for (int i = tid; i < NP; i += NTHR) {
            int r = i >> 7, hc = i & 127;
            int t = lrow0 + r;
            if (t < nrows) {
                float v = s_p[i] + s_p[NP + i] + s_p[2 * NP + i] + s_p[3 * NP + i];
                if (is_atom) g_proj_h[t * H_ + hc] = __float2half(v + b_in[hc]);
                else         g_proj_h[(NATOM + t) * H_ + hc] = __float2half(v);
            }
        }
        __syncthreads();
    }

    // Prefetch gather indices for this block's 8 molecules (pre-barrier overlap).
    // Atom index -> uint2 index into SMEM table; fp index -> uint2 index into global.
    int* s_ia = (int*)s_r1;            // [8][128]
    int* s_if = ((int*)s_r1) + 1024;   // [8][128]
    for (int i = tid; i < 8 * A_; i += NTHR) {
        s_ia[i] = atom_features[blk * 8 * A_ + i] * (H_ / 4);
        s_if[i] = (NATOM + fingerprints[blk * 8 * A_ + i]) * (H_ / 4);
    }

    const unsigned epoch = flat_barrier_epoch(&s_ep);   // g_proj_h complete

    // Copy atom table (100 rows x 256B fp16 = 25.6 KB) into shared.
    {
        const uint4* src = (const uint4*)g_proj_h;      // first 1600 uint4
        uint4* dst = (uint4*)s_atab;
        for (int i = tid; i < (NATOM * H_ * 2) / 16; i += NTHR) dst[i] = src[i];
        __syncthreads();
    }

    // ---------------- Phase C: per-molecule mean of relu(A+F) ----------------
    // Warp w (0..31): molecule blk*8 + (w>>2), atom quarter (w&3)*32.
    // Atom row from SMEM (LDS.64), fp row from L2 (LDG.64), 256B per warp-row.
    {
        float* s_part = s_r2;                           // [32][128]
        const uint2* __restrict__ gp = (const uint2*)g_proj_h;
        const uint2* at = (const uint2*)s_atab;
        const int w    = tid >> 5;
        const int lane = tid & 31;
        const int ml   = w >> 2;
        const int a0   = (w & 3) * 32;
        const int* ia  = s_ia + ml * A_ + a0;
        const int* ifp = s_if + ml * A_ + a0;
        const __half2 zero2 = __float2half2_rn(0.0f);

        float4 acc = make_float4(0.0f, 0.0f, 0.0f, 0.0f);
        #pragma unroll 8
        for (int a = 0; a < 32; a++) {
            uint2 ua = at[ia[a] + lane];                // LDS.64, conflict-free
            uint2 uf = gp[ifp[a] + lane];               // LDG.64
            __half2 va0 = *(__half2*)&ua.x, va1 = *(__half2*)&ua.y;
            __half2 vf0 = *(__half2*)&uf.x, vf1 = *(__half2*)&uf.y;
            __half2 s0 = __hmax2(__hadd2(va0, vf0), zero2);
            __half2 s1 = __hmax2(__hadd2(va1, vf1), zero2);
            float2 p0 = __half22float2(s0);
            float2 p1 = __half22float2(s1);
            acc.x += p0.x; acc.y += p0.y; acc.z += p1.x; acc.w += p1.y;
        }
        s_part[w * H_ + 4 * lane + 0] = acc.x;
        s_part[w * H_ + 4 * lane + 1] = acc.y;
        s_part[w * H_ + 4 * lane + 2] = acc.z;
        s_part[w * H_ + 4 * lane + 3] = acc.w;
        __syncthreads();

        {   // combine 4 atom-quarters, store 8 molecules
            int m = tid >> 7, d = tid & 127;
            float v = (s_part[(4 * m + 0) * H_ + d] + s_part[(4 * m + 1) * H_ + d] +
                       s_part[(4 * m + 2) * H_ + d] + s_part[(4 * m + 3) * H_ + d])
                      * (1.0f / (float)A_);
            g_mol[(blk * 8 + m) * H_ + d] = v;
        }
    }

    // Publish this block's molecules (monotonic flag; target == epoch).
    __threadfence();
    __syncthreads();
    if (tid == 0) atomicAdd(&g_flag[blk], 1u);

    // ---------------- Phase E: head (blocks 0..63) ----------------------------
    if (blk >= B_) return;

    // Wait only for the two producer blocks of batch b = blk.
    if (tid == 0) {
        const volatile unsigned* f = (const volatile unsigned*)g_flag;
        while (f[2 * blk] < epoch || f[2 * blk + 1] < epoch) { }
        __threadfence();
    }
    __syncthreads();

    {
        float* s_w   = s_r2;          // 16
        float* s_z   = s_r2 + 16;     // 144
        float* s_zn  = s_r2 + 160;    // 144
        float* s_red = s_r2 + 304;    // 8
        const int b = blk;
        const int h = tid;            // tid<128 active; all threads hit syncs

        if (h < M_) s_w[h] = ratios[b * M_ + h];
        __syncthreads();
        if (h == 0) {
            float s = 0.0f;
            #pragma unroll
            for (int m = 0; m < M_; m++) s += s_w[m];
            float inv = 1.0f / (s + 1e-8f);
            #pragma unroll
            for (int m = 0; m < M_; m++) s_w[m] *= inv;
        }
        __syncthreads();

        if (h < H_) {
            float acc = 0.0f;
            #pragma unroll
            for (int m = 0; m < M_; m++) acc += s_w[m] * g_mol[(b * M_ + m) * H_ + h];
            s_z[h] = acc;
            if (h < P_) {
                float accp = 0.0f;
                #pragma unroll
                for (int m = 0; m < M_; m++) {
                    float v = phys[(b * M_ + m) * P_ + h];
                    if (v != v) v = 0.0f;
                    else if (isinf(v)) v = (v > 0.0f) ? 1000.0f : -1000.0f;
                    accp += s_w[m] * v;
                }
                s_z[H_ + h] = accp;
            }
        }
        __syncthreads();

        if (h < H_) {
            float x  = s_z[h];
            float x2 = x * x;
            if (h < P_) { float e = s_z[H_ + h]; x += e; x2 += e * e; }
            #pragma unroll
            for (int o = 16; o > 0; o >>= 1) {
                x  += __shfl_xor_sync(0xFFFFFFFFu, x,  o);
                x2 += __shfl_xor_sync(0xFFFFFFFFu, x2, o);
            }
            int warp = h >> 5;
            if ((h & 31) == 0) { s_red[warp] = x; s_red[4 + warp] = x2; }
        }
        __syncthreads();

        if (h < H_) {
            float sum  = s_red[0] + s_red[1] + s_red[2] + s_red[3];
            float sum2 = s_red[4] + s_red[5] + s_red[6] + s_red[7];
            const float N = (float)(H_ + P_);
            float mu  = sum / N;
            float var = sum2 / N - mu * mu;
            float rstd = rsqrtf(var + 1e-5f);
            s_zn[h] = (s_z[h] - mu) * rstd * ln_g[h] + ln_b[h];
            if (h < P_) s_zn[H_ + h] = (s_z[H_ + h] - mu) * rstd * ln_g[H_ + h] + ln_b[H_ + h];
        }
        __syncthreads();

        if (h < H_) {
            float t = b1[h];
            #pragma unroll 4
            for (int d = 0; d < H_ + P_; d++) t += s_zn[d] * W1[d * H_ + h];
            float r = fmaxf(t, 0.0f) * W2[h];
            #pragma unroll
            for (int o = 16; o > 0; o >>= 1) r += __shfl_xor_sync(0xFFFFFFFFu, r, o);
            int warp = h >> 5;
            if ((h & 31) == 0) s_red[warp] = r;
        }
        __syncthreads();

        if (h == 0) {
            float y = s_red[0] + s_red[1] + s_red[2] + s_red[3] + b2[0];
            if (y != y) y = 0.0f;
            else if (isinf(y)) y = (y > 0.0f) ? 3.4028234663852886e38f : -3.4028234663852886e38f;
            out[b] = y;
        }
    }
}

extern "C" void kernel_launch(void* const* d_in, const int* in_sizes, int n_in,
                              void* d_out, int out_size) {
    const int*   atom_features = (const int*)  d_in[0];
    const int*   fingerprints  = (const int*)  d_in[1];
    const float* phys          = (const float*)d_in[2];
    const float* ratios        = (const float*)d_in[3];
    const float* atom_emb      = (const float*)d_in[4];
    const float* fp_emb        = (const float*)d_in[5];
    const float* W_in          = (const float*)d_in[6];
    const float* b_in          = (const float*)d_in[7];
    const float* ln_g          = (const float*)d_in[8];
    const float* ln_b          = (const float*)d_in[9];
    const float* W1            = (const float*)d_in[10];
    const float* b1            = (const float*)d_in[11];
    const float* W2            = (const float*)d_in[12];
    const float* b2            = (const float*)d_in[13];
    float* out = (float*)d_out;

    cudaFuncSetAttribute(fused_kernel,
                         cudaFuncAttributeMaxDynamicSharedMemorySize, SMEM_DYN);
    fused_kernel<<<GRID, NTHR, SMEM_DYN>>>(atom_features, fingerprints, phys, ratios,
                                           atom_emb, fp_emb, W_in, b_in, ln_g, ln_b,
                                           W1, b1, W2, b2, out);
}

// round 8
// speedup vs baseline: 1.3808x; 1.3808x over previous
#include <cuda_runtime.h>
#include <cuda_fp16.h>
#include <math.h>

#define B_  64
#define M_  16
#define A_  128
#define H_  128
#define P_  16
#define NATOM 100
#define NFP   2048
#define NTAB  (NATOM + NFP)     // 2148
#define RPB   17                // table rows per block in proj kernel

// Scratch (__device__ globals: allocation-free rule)
__device__ __half g_proj_h[NTAB * H_];    // projected tables, fp16 (0.55 MB, L2-resident)
__device__ float  g_mol[B_ * M_ * H_];    // per-molecule mean embeddings

// ---------------------------------------------------------------------------
// Kernel 1: projected tables -> g_proj_h (fp16).
// Blocks 0..5: 100 atom rows (+b_in, W top half). Blocks 6..127: 2048 fp rows
// (W bottom half), 17 rows each (last partial). 1024 threads:
// h = tid&127 (out col), ks = (tid>>7)&3 (32 K-steps), rh = tid>>9 (row half).
// ---------------------------------------------------------------------------
__global__ __launch_bounds__(1024, 1)
void proj_kernel(const float* __restrict__ atom_emb,
                 const float* __restrict__ fp_emb,
                 const float* __restrict__ W_in,
                 const float* __restrict__ b_in) {
    __shared__ __align__(16) float s_eT[2560];            // [d][r] stride 20
    __shared__ __align__(16) float s_p[4 * RPB * H_];     // [ks][r][h]

    const int tid = threadIdx.x;
    const int blk = blockIdx.x;
    const int h  = tid & 127;
    const int ks = (tid >> 7) & 3;
    const int rh = tid >> 9;
    const int r0 = rh ? 8 : 0;
    const bool is_atom = (blk < 6);
    const int lrow0 = is_atom ? blk * RPB : (blk - 6) * RPB;
    const int nrows = is_atom ? NATOM : NFP;
    const int wbase = is_atom ? 0 : (H_ * H_);

    for (int i = tid; i < RPB * H_; i += 1024) {
        int r = i >> 7, d = i & 127;
        int t = lrow0 + r;
        float v = 0.0f;
        if (t < nrows) v = is_atom ? atom_emb[t * H_ + d] : fp_emb[t * H_ + d];
        s_eT[d * 20 + r] = v;
    }
    __syncthreads();

    const float* __restrict__ Wp = W_in + wbase + h;
    const int d0 = ks * 32;

    float acc[9];
    #pragma unroll
    for (int r = 0; r < 9; r++) acc[r] = 0.0f;

    #pragma unroll
    for (int chunk = 0; chunk < 2; chunk++) {
        float wreg[16];                                   // independent LDG batch (MLP=16)
        #pragma unroll
        for (int i = 0; i < 16; i++) wreg[i] = Wp[(d0 + chunk * 16 + i) * H_];

        #pragma unroll
        for (int dd = 0; dd < 16; dd++) {
            const float w = wreg[dd];
            const float* e = s_eT + (d0 + chunk * 16 + dd) * 20 + r0;
            const float4 e0 = *(const float4*)(e);
            const float4 e1 = *(const float4*)(e + 4);
            acc[0] += e0.x * w; acc[1] += e0.y * w; acc[2] += e0.z * w; acc[3] += e0.w * w;
            acc[4] += e1.x * w; acc[5] += e1.y * w; acc[6] += e1.z * w; acc[7] += e1.w * w;
            if (rh) acc[8] += e[8] * w;                   // 17th row (upper half only)
        }
    }

    const int nr = rh ? 9 : 8;
    #pragma unroll
    for (int r = 0; r < 9; r++)
        if (r < nr) s_p[(ks * RPB + r0 + r) * H_ + h] = acc[r];
    __syncthreads();

    const int NP = RPB * H_;
    for (int i = tid; i < NP; i += 1024) {
        int r = i >> 7, hc = i & 127;
        int t = lrow0 + r;
        if (t < nrows) {
            float v = s_p[i] + s_p[NP + i] + s_p[2 * NP + i] + s_p[3 * NP + i];
            if (is_atom) g_proj_h[t * H_ + hc] = __float2half(v + b_in[hc]);
            else         g_proj_h[(NATOM + t) * H_ + hc] = __float2half(v);
        }
    }
}

// ---------------------------------------------------------------------------
// Kernel 2: per-molecule mean of relu(A_proj[af] + F_proj[fp]).
// Grid 512 x 256 threads: 2 molecules/block, 8 warps, 32 atoms/warp.
// Indices live in registers (lane i holds atom i's row bases), broadcast via
// __shfl each iteration. One warp reads a 256B fp16 row per LDG.64.
// 8 blocks/SM -> 64 warps/SM of gather for latency hiding.
// ---------------------------------------------------------------------------
__global__ __launch_bounds__(256, 8)
void mol_kernel(const int* __restrict__ atom_features,
                const int* __restrict__ fingerprints) {
    __shared__ float s_part[8 * H_];                      // per-warp partials

    const int tid  = threadIdx.x;
    const int w    = tid >> 5;                            // 0..7
    const int lane = tid & 31;
    const int ml   = w >> 2;                              // molecule-in-block 0..1
    const int q    = w & 3;                               // atom quarter
    const int bm   = blockIdx.x * 2 + ml;

    // Lane i holds atom (q*32 + i)'s two row bases (uint2 units).
    const int abase = bm * A_ + q * 32 + lane;
    const int ra = atom_features[abase] * (H_ / 4);
    const int rf = (NATOM + fingerprints[abase]) * (H_ / 4);

    const uint2* __restrict__ gp = (const uint2*)g_proj_h;
    const __half2 zero2 = __float2half2_rn(0.0f);

    float4 acc = make_float4(0.0f, 0.0f, 0.0f, 0.0f);
    #pragma unroll 8
    for (int a = 0; a < 32; a++) {
        int ia = __shfl_sync(0xFFFFFFFFu, ra, a);
        int If = __shfl_sync(0xFFFFFFFFu, rf, a);
        uint2 ua = gp[ia + lane];
        uint2 uf = gp[If + lane];
        __half2 va0 = *(__half2*)&ua.x, va1 = *(__half2*)&ua.y;
        __half2 vf0 = *(__half2*)&uf.x, vf1 = *(__half2*)&uf.y;
        __half2 s0 = __hmax2(__hadd2(va0, vf0), zero2);
        __half2 s1 = __hmax2(__hadd2(va1, vf1), zero2);
        float2 p0 = __half22float2(s0);
        float2 p1 = __half22float2(s1);
        acc.x += p0.x; acc.y += p0.y; acc.z += p1.x; acc.w += p1.y;
    }
    s_part[w * H_ + 4 * lane + 0] = acc.x;
    s_part[w * H_ + 4 * lane + 1] = acc.y;
    s_part[w * H_ + 4 * lane + 2] = acc.z;
    s_part[w * H_ + 4 * lane + 3] = acc.w;
    __syncthreads();

    // 2 molecules x 128 dims = 256 outputs, one per thread.
    {
        int m = tid >> 7, d = tid & 127;
        float v = (s_part[(4 * m + 0) * H_ + d] + s_part[(4 * m + 1) * H_ + d] +
                   s_part[(4 * m + 2) * H_ + d] + s_part[(4 * m + 3) * H_ + d])
                  * (1.0f / (float)A_);
        g_mol[(blockIdx.x * 2 + m) * H_ + d] = v;
    }
}

// ---------------------------------------------------------------------------
// Kernel 3: mixing weights + phys mix + LayerNorm + 2-layer MLP head.
// One block per batch item; 128 threads.
// ---------------------------------------------------------------------------
__global__ __launch_bounds__(128)
void head_kernel(const float* __restrict__ phys,
                 const float* __restrict__ ratios,
                 const float* __restrict__ ln_g,
                 const float* __restrict__ ln_b,
                 const float* __restrict__ W1,
                 const float* __restrict__ b1,
                 const float* __restrict__ W2,
                 const float* __restrict__ b2,
                 float* __restrict__ out) {
    const int b = blockIdx.x;
    const int h = threadIdx.x;

    __shared__ float s_w[M_];
    __shared__ float s_z[H_ + P_];
    __shared__ float s_zn[H_ + P_];
    __shared__ float s_red[8];

    if (h < M_) s_w[h] = ratios[b * M_ + h];
    __syncthreads();
    if (h == 0) {
        float s = 0.0f;
        #pragma unroll
        for (int m = 0; m < M_; m++) s += s_w[m];
        float inv = 1.0f / (s + 1e-8f);
        #pragma unroll
        for (int m = 0; m < M_; m++) s_w[m] *= inv;
    }
    __syncthreads();

    float acc = 0.0f;
    #pragma unroll
    for (int m = 0; m < M_; m++) acc += s_w[m] * g_mol[(b * M_ + m) * H_ + h];
    s_z[h] = acc;
    if (h < P_) {
        float accp = 0.0f;
        #pragma unroll
        for (int m = 0; m < M_; m++) {
            float v = phys[(b * M_ + m) * P_ + h];
            if (v != v) v = 0.0f;
            else if (isinf(v)) v = (v > 0.0f) ? 1000.0f : -1000.0f;
            accp += s_w[m] * v;
        }
        s_z[H_ + h] = accp;
    }
    __syncthreads();

    float x  = s_z[h];
    float x2 = x * x;
    if (h < P_) { float e = s_z[H_ + h]; x += e; x2 += e * e; }
    #pragma unroll
    for (int o = 16; o > 0; o >>= 1) {
        x  += __shfl_xor_sync(0xFFFFFFFFu, x,  o);
        x2 += __shfl_xor_sync(0xFFFFFFFFu, x2, o);
    }
    int warp = h >> 5;
    if ((h & 31) == 0) { s_red[warp] = x; s_red[4 + warp] = x2; }
    __syncthreads();
    float sum  = s_red[0] + s_red[1] + s_red[2] + s_red[3];
    float sum2 = s_red[4] + s_red[5] + s_red[6] + s_red[7];
    const float N = (float)(H_ + P_);
    float mu  = sum / N;
    float var = sum2 / N - mu * mu;
    float rstd = rsqrtf(var + 1e-5f);

    s_zn[h] = (s_z[h] - mu) * rstd * ln_g[h] + ln_b[h];
    if (h < P_) s_zn[H_ + h] = (s_z[H_ + h] - mu) * rstd * ln_g[H_ + h] + ln_b[H_ + h];
    __syncthreads();

    float t = b1[h];
    #pragma unroll 4
    for (int d = 0; d < H_ + P_; d++) t += s_zn[d] * W1[d * H_ + h];
    float r = fmaxf(t, 0.0f) * W2[h];

    #pragma unroll
    for (int o = 16; o > 0; o >>= 1) r += __shfl_xor_sync(0xFFFFFFFFu, r, o);
    if ((h & 31) == 0) s_red[warp] = r;
    __syncthreads();
    if (h == 0) {
        float y = s_red[0] + s_red[1] + s_red[2] + s_red[3] + b2[0];
        if (y != y) y = 0.0f;
        else if (isinf(y)) y = (y > 0.0f) ? 3.4028234663852886e38f : -3.4028234663852886e38f;
        out[b] = y;
    }
}

extern "C" void kernel_launch(void* const* d_in, const int* in_sizes, int n_in,
                              void* d_out, int out_size) {
    const int*   atom_features = (const int*)  d_in[0];
    const int*   fingerprints  = (const int*)  d_in[1];
    const float* phys          = (const float*)d_in[2];
    const float* ratios        = (const float*)d_in[3];
    const float* atom_emb      = (const float*)d_in[4];
    const float* fp_emb        = (const float*)d_in[5];
    const float* W_in          = (const float*)d_in[6];
    const float* b_in          = (const float*)d_in[7];
    const float* ln_g          = (const float*)d_in[8];
    const float* ln_b          = (const float*)d_in[9];
    const float* W1            = (const float*)d_in[10];
    const float* b1            = (const float*)d_in[11];
    const float* W2            = (const float*)d_in[12];
    const float* b2            = (const float*)d_in[13];
    float* out = (float*)d_out;

    proj_kernel<<<128, 1024>>>(atom_emb, fp_emb, W_in, b_in);
    mol_kernel<<<512, 256>>>(atom_features, fingerprints);
    head_kernel<<<B_, 128>>>(phys, ratios, ln_g, ln_b, W1, b1, W2, b2, out);
}

// round 9
// speedup vs baseline: 1.6036x; 1.1613x over previous
#include <cuda_runtime.h>
#include <cuda_fp16.h>
#include <math.h>

#define B_  64
#define M_  16
#define A_  128
#define H_  128
#define P_  16
#define NATOM 100
#define NFP   2048
#define NTAB  (NATOM + NFP)     // 2148
#define RPB   17                // table rows per block in proj kernel

// Scratch (__device__ globals: allocation-free rule)
__device__ __half g_proj_h[NTAB * H_];    // projected tables, fp16 (0.55 MB, L2-resident)
__device__ float  g_mol[B_ * M_ * H_];    // per-molecule mean embeddings

// ---------------------------------------------------------------------------
// Kernel 1: projected tables -> g_proj_h (fp16).
// Blocks 0..5: 100 atom rows (+b_in, W top half). Blocks 6..127: 2048 fp rows
// (W bottom half), 17 rows each. 1024 threads:
// h = tid&127 (out col), ks = (tid>>7)&3 (32 K-steps), rh = tid>>9 (row half).
// W prefetched in 4 batches of 8 (not 16) to stay under the 64-reg cap: no spills.
// ---------------------------------------------------------------------------
__global__ __launch_bounds__(1024, 1)
void proj_kernel(const float* __restrict__ atom_emb,
                 const float* __restrict__ fp_emb,
                 const float* __restrict__ W_in,
                 const float* __restrict__ b_in) {
    __shared__ __align__(16) float s_eT[2560];            // [d][r] stride 20
    __shared__ __align__(16) float s_p[4 * RPB * H_];     // [ks][r][h]

    const int tid = threadIdx.x;
    const int blk = blockIdx.x;
    const int h  = tid & 127;
    const int ks = (tid >> 7) & 3;
    const int rh = tid >> 9;
    const int r0 = rh ? 8 : 0;
    const bool is_atom = (blk < 6);
    const int lrow0 = is_atom ? blk * RPB : (blk - 6) * RPB;
    const int nrows = is_atom ? NATOM : NFP;
    const int wbase = is_atom ? 0 : (H_ * H_);

    for (int i = tid; i < RPB * H_; i += 1024) {
        int r = i >> 7, d = i & 127;
        int t = lrow0 + r;
        float v = 0.0f;
        if (t < nrows) v = is_atom ? atom_emb[t * H_ + d] : fp_emb[t * H_ + d];
        s_eT[d * 20 + r] = v;
    }
    __syncthreads();

    const float* __restrict__ Wp = W_in + wbase + h;
    const int d0 = ks * 32;

    float acc[9];
    #pragma unroll
    for (int r = 0; r < 9; r++) acc[r] = 0.0f;

    #pragma unroll
    for (int chunk = 0; chunk < 4; chunk++) {
        float wreg[8];                                    // small batch: no spills
        #pragma unroll
        for (int i = 0; i < 8; i++) wreg[i] = Wp[(d0 + chunk * 8 + i) * H_];

        #pragma unroll
        for (int dd = 0; dd < 8; dd++) {
            const float w = wreg[dd];
            const float* e = s_eT + (d0 + chunk * 8 + dd) * 20 + r0;
            const float4 e0 = *(const float4*)(e);
            const float4 e1 = *(const float4*)(e + 4);
            acc[0] += e0.x * w; acc[1] += e0.y * w; acc[2] += e0.z * w; acc[3] += e0.w * w;
            acc[4] += e1.x * w; acc[5] += e1.y * w; acc[6] += e1.z * w; acc[7] += e1.w * w;
            if (rh) acc[8] += e[8] * w;                   // 17th row (upper half only)
        }
    }

    const int nr = rh ? 9 : 8;
    #pragma unroll
    for (int r = 0; r < 9; r++)
        if (r < nr) s_p[(ks * RPB + r0 + r) * H_ + h] = acc[r];
    __syncthreads();

    const int NP = RPB * H_;
    for (int i = tid; i < NP; i += 1024) {
        int r = i >> 7, hc = i & 127;
        int t = lrow0 + r;
        if (t < nrows) {
            float v = s_p[i] + s_p[NP + i] + s_p[2 * NP + i] + s_p[3 * NP + i];
            if (is_atom) g_proj_h[t * H_ + hc] = __float2half(v + b_in[hc]);
            else         g_proj_h[(NATOM + t) * H_ + hc] = __float2half(v);
        }
    }
}

// ---------------------------------------------------------------------------
// Kernel 2: per-molecule mean of relu(A_proj[af] + F_proj[fp]).
// Grid 512 x 256 threads: 2 molecules/block, 8 warps, 32 atoms/warp.
// Lane i holds atom i's row bases; __shfl broadcasts per iteration. One warp
// reads a 256B fp16 row per LDG.64. Partials stored via STS.128 (conflict-free).
// ---------------------------------------------------------------------------
__global__ __launch_bounds__(256, 8)
void mol_kernel(const int* __restrict__ atom_features,
                const int* __restrict__ fingerprints) {
    __shared__ __align__(16) float s_part[8 * H_];        // [warp][dim], float4 strided

    const int tid  = threadIdx.x;
    const int w    = tid >> 5;                            // 0..7
    const int lane = tid & 31;
    const int ml   = w >> 2;                              // molecule-in-block 0..1
    const int q    = w & 3;                               // atom quarter
    const int bm   = blockIdx.x * 2 + ml;

    const int abase = bm * A_ + q * 32 + lane;
    const int ra = atom_features[abase] * (H_ / 4);       // uint2-row base
    const int rf = (NATOM + fingerprints[abase]) * (H_ / 4);

    const uint2* __restrict__ gp = (const uint2*)g_proj_h;
    const __half2 zero2 = __float2half2_rn(0.0f);

    float4 acc = make_float4(0.0f, 0.0f, 0.0f, 0.0f);
    #pragma unroll 8
    for (int a = 0; a < 32; a++) {
        int ia = __shfl_sync(0xFFFFFFFFu, ra, a);
        int If = __shfl_sync(0xFFFFFFFFu, rf, a);
        uint2 ua = gp[ia + lane];
        uint2 uf = gp[If + lane];
        __half2 va0 = *(__half2*)&ua.x, va1 = *(__half2*)&ua.y;
        __half2 vf0 = *(__half2*)&uf.x, vf1 = *(__half2*)&uf.y;
        __half2 s0 = __hmax2(__hadd2(va0, vf0), zero2);
        __half2 s1 = __hmax2(__hadd2(va1, vf1), zero2);
        float2 p0 = __half22float2(s0);
        float2 p1 = __half22float2(s1);
        acc.x += p0.x; acc.y += p0.y; acc.z += p1.x; acc.w += p1.y;
    }
    ((float4*)s_part)[w * 32 + lane] = acc;               // one STS.128, conflict-free
    __syncthreads();

    // 2 molecules x 128 dims = 256 outputs, one per thread.
    {
        int m = tid >> 7, d = tid & 127;
        float v = (s_part[(4 * m + 0) * H_ + d] + s_part[(4 * m + 1) * H_ + d] +
                   s_part[(4 * m + 2) * H_ + d] + s_part[(4 * m + 3) * H_ + d])
                  * (1.0f / (float)A_);
        g_mol[(blockIdx.x * 2 + m) * H_ + d] = v;
    }
}

// ---------------------------------------------------------------------------
// Kernel 3: mixing weights + phys mix + LayerNorm + 2-layer MLP head.
// One block per batch item; 256 threads (W1 GEMV 2-way K-split).
// ---------------------------------------------------------------------------
__global__ __launch_bounds__(256)
void head_kernel(const float* __restrict__ phys,
                 const float* __restrict__ ratios,
                 const float* __restrict__ ln_g,
                 const float* __restrict__ ln_b,
                 const float* __restrict__ W1,
                 const float* __restrict__ b1,
                 const float* __restrict__ W2,
                 const float* __restrict__ b2,
                 float* __restrict__ out) {
    const int b   = blockIdx.x;
    const int tid = threadIdx.x;
    const int h   = tid & 127;
    const int ks  = tid >> 7;          // 0,1: K-split of the W1 GEMV

    __shared__ float s_w[M_];
    __shared__ float s_z[H_ + P_];
    __shared__ float s_zn[H_ + P_];
    __shared__ float s_red[8];
    __shared__ float s_t[2][H_];

    if (tid < M_) s_w[tid] = ratios[b * M_ + tid];
    __syncthreads();
    if (tid == 0) {
        float s = 0.0f;
        #pragma unroll
        for (int m = 0; m < M_; m++) s += s_w[m];
        float inv = 1.0f / (s + 1e-8f);
        #pragma unroll
        for (int m = 0; m < M_; m++) s_w[m] *= inv;
    }
    __syncthreads();

    if (tid < H_) {
        float acc = 0.0f;
        #pragma unroll
        for (int m = 0; m < M_; m++) acc += s_w[m] * g_mol[(b * M_ + m) * H_ + tid];
        s_z[tid] = acc;
        if (tid < P_) {
            float accp = 0.0f;
            #pragma unroll
            for (int m = 0; m < M_; m++) {
                float v = phys[(b * M_ + m) * P_ + tid];
                if (v != v) v = 0.0f;
                else if (isinf(v)) v = (v > 0.0f) ? 1000.0f : -1000.0f;
                accp += s_w[m] * v;
            }
            s_z[H_ + tid] = accp;
        }
    }
    __syncthreads();

    if (tid < H_) {
        float x  = s_z[tid];
        float x2 = x * x;
        if (tid < P_) { float e = s_z[H_ + tid]; x += e; x2 += e * e; }
        #pragma unroll
        for (int o = 16; o > 0; o >>= 1) {
            x  += __shfl_xor_sync(0xFFFFFFFFu, x,  o);
            x2 += __shfl_xor_sync(0xFFFFFFFFu, x2, o);
        }
        int warp = tid >> 5;
        if ((tid & 31) == 0) { s_red[warp] = x; s_red[4 + warp] = x2; }
    }
    __syncthreads();

    if (tid < H_) {
        float sum  = s_red[0] + s_red[1] + s_red[2] + s_red[3];
        float sum2 = s_red[4] + s_red[5] + s_red[6] + s_red[7];
        const float N = (float)(H_ + P_);
        float mu  = sum / N;
        float var = sum2 / N - mu * mu;
        float rstd = rsqrtf(var + 1e-5f);
        s_zn[tid] = (s_z[tid] - mu) * rstd * ln_g[tid] + ln_b[tid];
        if (tid < P_) s_zn[H_ + tid] = (s_z[H_ + tid] - mu) * rstd * ln_g[H_ + tid] + ln_b[H_ + tid];
    }
    __syncthreads();

    // W1 GEMV, 2-way K-split: ks=0 -> d in [0,72), ks=1 -> d in [72,144)
    {
        float t = (ks == 0) ? b1[h] : 0.0f;
        const int dlo = ks * 72;
        #pragma unroll 8
        for (int d = 0; d < 72; d++) t += s_zn[dlo + d] * W1[(dlo + d) * H_ + h];
        s_t[ks][h] = t;
    }
    __syncthreads();

    if (tid < H_) {
        float r = fmaxf(s_t[0][tid] + s_t[1][tid], 0.0f) * W2[tid];
        #pragma unroll
        for (int o = 16; o > 0; o >>= 1) r += __shfl_xor_sync(0xFFFFFFFFu, r, o);
        int warp = tid >> 5;
        if ((tid & 31) == 0) s_red[warp] = r;
    }
    __syncthreads();
    if (tid == 0) {
        float y = s_red[0] + s_red[1] + s_red[2] + s_red[3] + b2[0];
        if (y != y) y = 0.0f;
        else if (isinf(y)) y = (y > 0.0f) ? 3.4028234663852886e38f : -3.4028234663852886e38f;
        out[b] = y;
    }
}

extern "C" void kernel_launch(void* const* d_in, const int* in_sizes, int n_in,
                              void* d_out, int out_size) {
    const int*   atom_features = (const int*)  d_in[0];
    const int*   fingerprints  = (const int*)  d_in[1];
    const float* phys          = (const float*)d_in[2];
    const float* ratios        = (const float*)d_in[3];
    const float* atom_emb      = (const float*)d_in[4];
    const float* fp_emb        = (const float*)d_in[5];
    const float* W_in          = (const float*)d_in[6];
    const float* b_in          = (const float*)d_in[7];
    const float* ln_g          = (const float*)d_in[8];
    const float* ln_b          = (const float*)d_in[9];
    const float* W1            = (const float*)d_in[10];
    const float* b1            = (const float*)d_in[11];
    const float* W2            = (const float*)d_in[12];
    const float* b2            = (const float*)d_in[13];
    float* out = (float*)d_out;

    proj_kernel<<<128, 1024>>>(atom_emb, fp_emb, W_in, b_in);
    mol_kernel<<<512, 256>>>(atom_features, fingerprints);
    head_kernel<<<B_, 256>>>(phys, ratios, ln_g, ln_b, W1, b1, W2, b2, out);
}

// round 10
// speedup vs baseline: 1.6058x; 1.0014x over previous
#include <cuda_runtime.h>
#include <cuda_fp16.h>
#include <math.h>

#define B_  64
#define M_  16
#define A_  128
#define H_  128
#define P_  16
#define NATOM 100
#define NFP   2048
#define NTAB  (NATOM + NFP)     // 2148
#define RPB   17                // table rows per block in proj kernel

// Scratch (__device__ globals: allocation-free rule)
__device__ __half g_proj_h[NTAB * H_];    // projected tables, fp16 (0.55 MB, L2-resident)
__device__ float  g_mol[B_ * M_ * H_];    // per-molecule mean embeddings

// ---- packed fp32x2 helpers (sm_100+: double-rate FFMA2, full fp32 precision) ----
__device__ __forceinline__ unsigned long long pack_f32x2(float x, float y) {
    unsigned long long r;
    asm("mov.b64 %0, {%1,%2};" : "=l"(r) : "f"(x), "f"(y));
    return r;
}
__device__ __forceinline__ void fma_f32x2(unsigned long long& d,
                                          unsigned long long a,
                                          unsigned long long b) {
    asm("fma.rn.f32x2 %0, %1, %2, %3;" : "=l"(d) : "l"(a), "l"(b), "l"(d));
}
__device__ __forceinline__ void unpack_f32x2(unsigned long long v, float& lo, float& hi) {
    asm("mov.b64 {%0,%1}, %2;" : "=f"(lo), "=f"(hi) : "l"(v));
}

// ---------------------------------------------------------------------------
// Kernel 1: projected tables -> g_proj_h (fp16).
// Blocks 0..5: 100 atom rows (+b_in, W top half). Blocks 6..127: 2048 fp rows
// (W bottom half), 17 rows each. 1024 threads:
// h = tid&127 (out col), ks = (tid>>7)&3 (32 K-steps), rh = tid>>9 (row half).
// Inner loop uses fma.rn.f32x2: 8 packed rows per thread-half (+ row 16 scalar).
// ---------------------------------------------------------------------------
__global__ __launch_bounds__(1024, 1)
void proj_kernel(const float* __restrict__ atom_emb,
                 const float* __restrict__ fp_emb,
                 const float* __restrict__ W_in,
                 const float* __restrict__ b_in) {
    __shared__ __align__(16) float s_eT[2560];            // [d][r] stride 20
    __shared__ __align__(16) float s_p[4 * RPB * H_];     // [ks][r][h]

    const int tid = threadIdx.x;
    const int blk = blockIdx.x;
    const int h  = tid & 127;
    const int ks = (tid >> 7) & 3;
    const int rh = tid >> 9;
    const int r0 = rh ? 8 : 0;
    const bool is_atom = (blk < 6);
    const int lrow0 = is_atom ? blk * RPB : (blk - 6) * RPB;
    const int nrows = is_atom ? NATOM : NFP;
    const int wbase = is_atom ? 0 : (H_ * H_);

    for (int i = tid; i < RPB * H_; i += 1024) {
        int r = i >> 7, d = i & 127;
        int t = lrow0 + r;
        float v = 0.0f;
        if (t < nrows) v = is_atom ? atom_emb[t * H_ + d] : fp_emb[t * H_ + d];
        s_eT[d * 20 + r] = v;
    }
    __syncthreads();

    const float* __restrict__ Wp = W_in + wbase + h;
    const int d0 = ks * 32;

    unsigned long long acc2[4] = {0ull, 0ull, 0ull, 0ull};   // rows r0..r0+7 packed
    float acc16 = 0.0f;                                      // row 16 (rh half only)

    #pragma unroll
    for (int chunk = 0; chunk < 4; chunk++) {
        float wreg[8];                                       // independent LDG batch
        #pragma unroll
        for (int i = 0; i < 8; i++) wreg[i] = Wp[(d0 + chunk * 8 + i) * H_];

        #pragma unroll
        for (int dd = 0; dd < 8; dd++) {
            const float w = wreg[dd];
            const unsigned long long w2 = pack_f32x2(w, w);
            // rows r0..r0+7 as 4 packed f32x2 via two LDS.128 (16B-aligned)
            const ulonglong2* ep =
                (const ulonglong2*)(s_eT + (d0 + chunk * 8 + dd) * 20 + r0);
            ulonglong2 ea = ep[0];
            ulonglong2 eb = ep[1];
            fma_f32x2(acc2[0], ea.x, w2);
            fma_f32x2(acc2[1], ea.y, w2);
            fma_f32x2(acc2[2], eb.x, w2);
            fma_f32x2(acc2[3], eb.y, w2);
            if (rh) acc16 += ((const float*)ep)[8] * w;      // row 16
        }
    }

    {
        float racc[8];
        unpack_f32x2(acc2[0], racc[0], racc[1]);
        unpack_f32x2(acc2[1], racc[2], racc[3]);
        unpack_f32x2(acc2[2], racc[4], racc[5]);
        unpack_f32x2(acc2[3], racc[6], racc[7]);
        #pragma unroll
        for (int r = 0; r < 8; r++) s_p[(ks * RPB + r0 + r) * H_ + h] = racc[r];
        if (rh) s_p[(ks * RPB + 16) * H_ + h] = acc16;
    }
    __syncthreads();

    const int NP = RPB * H_;
    for (int i = tid; i < NP; i += 1024) {
        int r = i >> 7, hc = i & 127;
        int t = lrow0 + r;
        if (t < nrows) {
            float v = s_p[i] + s_p[NP + i] + s_p[2 * NP + i] + s_p[3 * NP + i];
            if (is_atom) g_proj_h[t * H_ + hc] = __float2half(v + b_in[hc]);
            else         g_proj_h[(NATOM + t) * H_ + hc] = __float2half(v);
        }
    }
}

// ---------------------------------------------------------------------------
// Kernel 2: per-molecule mean of relu(A_proj[af] + F_proj[fp]).
// Grid 512 x 256 threads: 2 molecules/block, 8 warps, 32 atoms/warp.
// Lane i holds atom i's row bases; __shfl broadcasts per iteration. One warp
// reads a 256B fp16 row per LDG.64. Partials stored via STS.128 (conflict-free).
// ---------------------------------------------------------------------------
__global__ __launch_bounds__(256, 8)
void mol_kernel(const int* __restrict__ atom_features,
                const int* __restrict__ fingerprints) {
    __shared__ __align__(16) float s_part[8 * H_];        // [warp][dim]

    const int tid  = threadIdx.x;
    const int w    = tid >> 5;                            // 0..7
    const int lane = tid & 31;
    const int ml   = w >> 2;                              // molecule-in-block 0..1
    const int q    = w & 3;                               // atom quarter
    const int bm   = blockIdx.x * 2 + ml;

    const int abase = bm * A_ + q * 32 + lane;
    const int ra = atom_features[abase] * (H_ / 4);       // uint2-row base
    const int rf = (NATOM + fingerprints[abase]) * (H_ / 4);

    const uint2* __restrict__ gp = (const uint2*)g_proj_h;
    const __half2 zero2 = __float2half2_rn(0.0f);

    float4 acc = make_float4(0.0f, 0.0f, 0.0f, 0.0f);
    #pragma unroll 8
    for (int a = 0; a < 32; a++) {
        int ia = __shfl_sync(0xFFFFFFFFu, ra, a);
        int If = __shfl_sync(0xFFFFFFFFu, rf, a);
        uint2 ua = gp[ia + lane];
        uint2 uf = gp[If + lane];
        __half2 va0 = *(__half2*)&ua.x, va1 = *(__half2*)&ua.y;
        __half2 vf0 = *(__half2*)&uf.x, vf1 = *(__half2*)&uf.y;
        __half2 s0 = __hmax2(__hadd2(va0, vf0), zero2);
        __half2 s1 = __hmax2(__hadd2(va1, vf1), zero2);
        float2 p0 = __half22float2(s0);
        float2 p1 = __half22float2(s1);
        acc.x += p0.x; acc.y += p0.y; acc.z += p1.x; acc.w += p1.y;
    }
    ((float4*)s_part)[w * 32 + lane] = acc;               // one STS.128, conflict-free
    __syncthreads();

    {
        int m = tid >> 7, d = tid & 127;
        float v = (s_part[(4 * m + 0) * H_ + d] + s_part[(4 * m + 1) * H_ + d] +
                   s_part[(4 * m + 2) * H_ + d] + s_part[(4 * m + 3) * H_ + d])
                  * (1.0f / (float)A_);
        g_mol[(blockIdx.x * 2 + m) * H_ + d] = v;
    }
}

// ---------------------------------------------------------------------------
// Kernel 3: mixing weights + phys mix + LayerNorm + 2-layer MLP head.
// One block per batch item; 256 threads (W1 GEMV 2-way K-split).
// ---------------------------------------------------------------------------
__global__ __launch_bounds__(256)
void head_kernel(const float* __restrict__ phys,
                 const float* __restrict__ ratios,
                 const float* __restrict__ ln_g,
                 const float* __restrict__ ln_b,
                 const float* __restrict__ W1,
                 const float* __restrict__ b1,
                 const float* __restrict__ W2,
                 const float* __restrict__ b2,
                 float* __restrict__ out) {
    const int b   = blockIdx.x;
    const int tid = threadIdx.x;
    const int h   = tid & 127;
    const int ks  = tid >> 7;          // 0,1: K-split of the W1 GEMV

    __shared__ float s_w[M_];
    __shared__ float s_z[H_ + P_];
    __shared__ float s_zn[H_ + P_];
    __shared__ float s_red[8];
    __shared__ float s_t[2][H_];

    if (tid < M_) s_w[tid] = ratios[b * M_ + tid];
    __syncthreads();
    if (tid == 0) {
        float s = 0.0f;
        #pragma unroll
        for (int m = 0; m < M_; m++) s += s_w[m];
        float inv = 1.0f / (s + 1e-8f);
        #pragma unroll
        for (int m = 0; m < M_; m++) s_w[m] *= inv;
    }
    __syncthreads();

    if (tid < H_) {
        float acc = 0.0f;
        #pragma unroll
        for (int m = 0; m < M_; m++) acc += s_w[m] * g_mol[(b * M_ + m) * H_ + tid];
        s_z[tid] = acc;
        if (tid < P_) {
            float accp = 0.0f;
            #pragma unroll
            for (int m = 0; m < M_; m++) {
                float v = phys[(b * M_ + m) * P_ + tid];
                if (v != v) v = 0.0f;
                else if (isinf(v)) v = (v > 0.0f) ? 1000.0f : -1000.0f;
                accp += s_w[m] * v;
            }
            s_z[H_ + tid] = accp;
        }
    }
    __syncthreads();

    if (tid < H_) {
        float x  = s_z[tid];
        float x2 = x * x;
        if (tid < P_) { float e = s_z[H_ + tid]; x += e; x2 += e * e; }
        #pragma unroll
        for (int o = 16; o > 0; o >>= 1) {
            x  += __shfl_xor_sync(0xFFFFFFFFu, x,  o);
            x2 += __shfl_xor_sync(0xFFFFFFFFu, x2, o);
        }
        int warp = tid >> 5;
        if ((tid & 31) == 0) { s_red[warp] = x; s_red[4 + warp] = x2; }
    }
    __syncthreads();

    if (tid < H_) {
        float sum  = s_red[0] + s_red[1] + s_red[2] + s_red[3];
        float sum2 = s_red[4] + s_red[5] + s_red[6] + s_red[7];
        const float N = (float)(H_ + P_);
        float mu  = sum / N;
        float var = sum2 / N - mu * mu;
        float rstd = rsqrtf(var + 1e-5f);
        s_zn[tid] = (s_z[tid] - mu) * rstd * ln_g[tid] + ln_b[tid];
        if (tid < P_) s_zn[H_ + tid] = (s_z[H_ + tid] - mu) * rstd * ln_g[H_ + tid] + ln_b[H_ + tid];
    }
    __syncthreads();

    // W1 GEMV, 2-way K-split: ks=0 -> d in [0,72), ks=1 -> d in [72,144)
    {
        float t = (ks == 0) ? b1[h] : 0.0f;
        const int dlo = ks * 72;
        #pragma unroll 8
        for (int d = 0; d < 72; d++) t += s_zn[dlo + d] * W1[(dlo + d) * H_ + h];
        s_t[ks][h] = t;
    }
    __syncthreads();

    if (tid < H_) {
        float r = fmaxf(s_t[0][tid] + s_t[1][tid], 0.0f) * W2[tid];
        #pragma unroll
        for (int o = 16; o > 0; o >>= 1) r += __shfl_xor_sync(0xFFFFFFFFu, r, o);
        int warp = tid >> 5;
        if ((tid & 31) == 0) s_red[warp] = r;
    }
    __syncthreads();
    if (tid == 0) {
        float y = s_red[0] + s_red[1] + s_red[2] + s_red[3] + b2[0];
        if (y != y) y = 0.0f;
        else if (isinf(y)) y = (y > 0.0f) ? 3.4028234663852886e38f : -3.4028234663852886e38f;
        out[b] = y;
    }
}

extern "C" void kernel_launch(void* const* d_in, const int* in_sizes, int n_in,
                              void* d_out, int out_size) {
    const int*   atom_features = (const int*)  d_in[0];
    const int*   fingerprints  = (const int*)  d_in[1];
    const float* phys          = (const float*)d_in[2];
    const float* ratios        = (const float*)d_in[3];
    const float* atom_emb      = (const float*)d_in[4];
    const float* fp_emb        = (const float*)d_in[5];
    const float* W_in          = (const float*)d_in[6];
    const float* b_in          = (const float*)d_in[7];
    const float* ln_g          = (const float*)d_in[8];
    const float* ln_b          = (const float*)d_in[9];
    const float* W1            = (const float*)d_in[10];
    const float* b1            = (const float*)d_in[11];
    const float* W2            = (const float*)d_in[12];
    const float* b2            = (const float*)d_in[13];
    float* out = (float*)d_out;

    proj_kernel<<<128, 1024>>>(atom_emb, fp_emb, W_in, b_in);
    mol_kernel<<<512, 256>>>(atom_features, fingerprints);
    head_kernel<<<B_, 256>>>(phys, ratios, ln_g, ln_b, W1, b1, W2, b2, out);
}